// round 9
// baseline (speedup 1.0000x reference)
#include <cuda_runtime.h>
#include <math.h>

// Problem constants: B=4, S=512, D=256
#define NB 4
#define NS 512
#define ND 256
#define NROWS (NB*NS)        // 2048
#define NPROJ (3*ND)         // 768

typedef unsigned long long ull;

// ---------------- f32x2 packed helpers ----------------
__device__ __forceinline__ void up2(ull v, float& x, float& y) {
    asm("mov.b64 {%0, %1}, %2;" : "=f"(x), "=f"(y) : "l"(v));
}
__device__ __forceinline__ ull fma2(ull a, ull b, ull c) {
    ull d; asm("fma.rn.f32x2 %0, %1, %2, %3;" : "=l"(d) : "l"(a), "l"(b), "l"(c)); return d;
}
__device__ __forceinline__ ull add2(ull a, ull b) {
    ull d; asm("add.rn.f32x2 %0, %1, %2;" : "=l"(d) : "l"(a), "l"(b)); return d;
}

// ---------------- scratch (device globals; no allocation) ----------------
__device__ float g_Beff[ND*NPROJ];          // [K=256][N=768]: (Wa+Wc)|(Wb-Wc)|Wv@Wo
__device__ float g_biasN[NPROJ];            // 0 | b1 | bv@Wo
__device__ float g_proj[NROWS*NPROJ];       // hi | hj+b1 | x@WvWo+bvWo  (6MB)
__device__ float g_scores[NB*NS*NS];        // scores -> attn in place (4MB)
__device__ float g_preln[NROWS*ND];         // x + attn@vWo + bo (2MB)

// ---------------- weight packing (cols 0..511 of Beff + biasN 0..511) -----
__global__ void pack_kernel(const float* __restrict__ W1,
                            const float* __restrict__ b1) {
    int idx = blockIdx.x * blockDim.x + threadIdx.x;   // 0..131071
    int k = idx >> 9;            // 0..255
    int n = idx & 511;           // 0..511
    float v;
    if (n < ND) v = W1[k*ND + n] + W1[(2*ND + k)*ND + n];
    else        v = W1[(ND + k)*ND + (n - ND)] - W1[(2*ND + k)*ND + (n - ND)];
    g_Beff[k*NPROJ + n] = v;
    if (idx < 512) g_biasN[idx] = (idx < ND) ? 0.f : b1[idx - ND];
}

// ---------------- bvWo: biasN[512+n] = sum_d bv[d]*Wo[d][n] --------------
__global__ void bvwo_kernel(const float* __restrict__ bv, const float* __restrict__ Wo) {
    __shared__ float part[8][32];
    const int nl = threadIdx.x & 31, dg = threadIdx.x >> 5;
    const int n = blockIdx.x * 32 + nl;
    float s = 0.f;
#pragma unroll
    for (int d = 0; d < 32; d++)
        s = fmaf(bv[dg*32 + d], Wo[(dg*32 + d)*ND + n], s);
    part[dg][nl] = s;
    __syncthreads();
    if (dg == 0) {
        float t = 0.f;
#pragma unroll
        for (int g = 0; g < 8; g++) t += part[g][nl];
        g_biasN[2*ND + n] = t;
    }
}

// ---------------- 64x64 GEMM, k-pair f32x2, double buffered ---------------
// As[row][k] (stride 36, natural copy), Bs[col][k] (stride 34, transposed).
// Thread (tx,ty): rows ty*4+i, cols tx+16g (strided). acc pairs along k.
// causal!=0 limits K to m0+64. K must be a multiple of 32.
__global__ __launch_bounds__(256)
void sgemm_kernel(const float* __restrict__ A, int lda, long sA,
                  const float* __restrict__ Bm, int ldb, long sB,
                  float* __restrict__ C, int ldc, long sC,
                  int K, int causal,
                  const float* __restrict__ bias,
                  const float* __restrict__ res, int ldres, long sRes) {
    __shared__ __align__(16) float As[2][64][36];
    __shared__ __align__(16) float Bs[2][64][34];
    long bz = blockIdx.z;
    A  += bz * sA;  Bm += bz * sB;  C += bz * sC;
    if (res) res += bz * sRes;
    const int m0 = blockIdx.y * 64, n0 = blockIdx.x * 64;
    const int Keff = causal ? (m0 + 64) : K;
    const int KT = Keff >> 5;
    const int tid = threadIdx.x;
    const int tx = tid & 15, ty = tid >> 4;
    const int rA = tid >> 3, qA = tid & 7;     // A loader: rows rA, rA+32; k-quad qA
    const int cB = tid & 63, qB = tid >> 6;    // B loader: col cB, k-quads qB, qB+4

    ull acc2[4][4];
#pragma unroll
    for (int i = 0; i < 4; i++)
#pragma unroll
        for (int g = 0; g < 4; g++) acc2[i][g] = 0ULL;

    // ---- prefetch + store tile 0 ----
    float4 pa0 = *(const float4*)&A[(long)(m0 + rA)*lda + qA*4];
    float4 pa1 = *(const float4*)&A[(long)(m0 + rA + 32)*lda + qA*4];
    float pb[8];
#pragma unroll
    for (int j = 0; j < 4; j++) {
        pb[j]     = Bm[(long)(qB*4 + j)*ldb + n0 + cB];
        pb[4 + j] = Bm[(long)((qB + 4)*4 + j)*ldb + n0 + cB];
    }
    *(float4*)&As[0][rA][qA*4]      = pa0;
    *(float4*)&As[0][rA + 32][qA*4] = pa1;
    *(float2*)&Bs[0][cB][qB*4]         = make_float2(pb[0], pb[1]);
    *(float2*)&Bs[0][cB][qB*4 + 2]     = make_float2(pb[2], pb[3]);
    *(float2*)&Bs[0][cB][(qB+4)*4]     = make_float2(pb[4], pb[5]);
    *(float2*)&Bs[0][cB][(qB+4)*4 + 2] = make_float2(pb[6], pb[7]);
    __syncthreads();

    int buf = 0;
    for (int kt = 0; kt < KT; kt++) {
        const int kkn = (kt + 1) << 5;
        if (kt + 1 < KT) {
            pa0 = *(const float4*)&A[(long)(m0 + rA)*lda + kkn + qA*4];
            pa1 = *(const float4*)&A[(long)(m0 + rA + 32)*lda + kkn + qA*4];
#pragma unroll
            for (int j = 0; j < 4; j++) {
                pb[j]     = Bm[(long)(kkn + qB*4 + j)*ldb + n0 + cB];
                pb[4 + j] = Bm[(long)(kkn + (qB + 4)*4 + j)*ldb + n0 + cB];
            }
        }
#pragma unroll 8
        for (int kp = 0; kp < 16; kp++) {
            ull a0 = *(const ull*)&As[buf][ty*4 + 0][2*kp];
            ull a1 = *(const ull*)&As[buf][ty*4 + 1][2*kp];
            ull a2 = *(const ull*)&As[buf][ty*4 + 2][2*kp];
            ull a3 = *(const ull*)&As[buf][ty*4 + 3][2*kp];
            ull b0 = *(const ull*)&Bs[buf][tx][2*kp];
            ull b1 = *(const ull*)&Bs[buf][tx + 16][2*kp];
            ull b2 = *(const ull*)&Bs[buf][tx + 32][2*kp];
            ull b3 = *(const ull*)&Bs[buf][tx + 48][2*kp];
            acc2[0][0] = fma2(a0, b0, acc2[0][0]);
            acc2[0][1] = fma2(a0, b1, acc2[0][1]);
            acc2[0][2] = fma2(a0, b2, acc2[0][2]);
            acc2[0][3] = fma2(a0, b3, acc2[0][3]);
            acc2[1][0] = fma2(a1, b0, acc2[1][0]);
            acc2[1][1] = fma2(a1, b1, acc2[1][1]);
            acc2[1][2] = fma2(a1, b2, acc2[1][2]);
            acc2[1][3] = fma2(a1, b3, acc2[1][3]);
            acc2[2][0] = fma2(a2, b0, acc2[2][0]);
            acc2[2][1] = fma2(a2, b1, acc2[2][1]);
            acc2[2][2] = fma2(a2, b2, acc2[2][2]);
            acc2[2][3] = fma2(a2, b3, acc2[2][3]);
            acc2[3][0] = fma2(a3, b0, acc2[3][0]);
            acc2[3][1] = fma2(a3, b1, acc2[3][1]);
            acc2[3][2] = fma2(a3, b2, acc2[3][2]);
            acc2[3][3] = fma2(a3, b3, acc2[3][3]);
        }
        if (kt + 1 < KT) {
            int nb = buf ^ 1;
            *(float4*)&As[nb][rA][qA*4]      = pa0;
            *(float4*)&As[nb][rA + 32][qA*4] = pa1;
            *(float2*)&Bs[nb][cB][qB*4]         = make_float2(pb[0], pb[1]);
            *(float2*)&Bs[nb][cB][qB*4 + 2]     = make_float2(pb[2], pb[3]);
            *(float2*)&Bs[nb][cB][(qB+4)*4]     = make_float2(pb[4], pb[5]);
            *(float2*)&Bs[nb][cB][(qB+4)*4 + 2] = make_float2(pb[6], pb[7]);
        }
        __syncthreads();
        buf ^= 1;
    }

    // ---- epilogue: horizontal add, bias/res, strided-col stores ----
#pragma unroll
    for (int i = 0; i < 4; i++) {
        int gm = m0 + ty*4 + i;
#pragma unroll
        for (int g = 0; g < 4; g++) {
            int gn = n0 + tx + 16*g;
            float lo, hi;
            up2(acc2[i][g], lo, hi);
            float t = lo + hi;
            if (bias) t += bias[gn];
            if (res)  t += res[(long)gm*ldres + gn];
            C[(long)gm*ldc + gn] = t;
        }
    }
}

// ---------------- pairwise relu-dot scores, h-pair f32x2 ------------------
// scores[b,i,j] = sum_h relu(hi[i,h] + hjb[j,h]) * w2[h] + b2
// relu(x)*w == (x + |x|) * (0.5*w)  exactly;  pairs along h, no splats.
__global__ __launch_bounds__(256)
void scores_kernel(const float* __restrict__ w2, const float* __restrict__ b2) {
    __shared__ __align__(16) float His[64][34];
    __shared__ __align__(16) float Hjs[64][34];
    __shared__ float w2s[ND];
    const int b = blockIdx.y;
    const int t = blockIdx.x;
    int ti = (int)((sqrtf(8.f*t + 1.f) - 1.f) * 0.5f);
    while ((ti + 1)*(ti + 2)/2 <= t) ti++;
    while (ti*(ti + 1)/2 > t) ti--;
    const int tj = t - ti*(ti + 1)/2;
    const int i0 = ti * 64, j0 = tj * 64;
    const int tid = threadIdx.x;
    w2s[tid] = 0.5f * w2[tid];
    const int tx = tid & 15, ty = tid >> 4;
    const int rL = tid >> 3, qL = tid & 7;     // loader rows rL, rL+32; h-quad qL
    const float* hiBase = g_proj + (long)(b*NS + i0) * NPROJ;         // hi cols
    const float* hjBase = g_proj + (long)(b*NS + j0) * NPROJ + ND;    // hj+b1 cols
    const float b2v = b2[0];
    const ull ABS2 = 0x7FFFFFFF7FFFFFFFULL;

    ull acc2[4][4];
#pragma unroll
    for (int i = 0; i < 4; i++)
#pragma unroll
        for (int g = 0; g < 4; g++) acc2[i][g] = 0ULL;

    for (int kk = 0; kk < ND; kk += 32) {
        __syncthreads();
#pragma unroll
        for (int l = 0; l < 2; l++) {
            int r = rL + l*32;
            float4 va = *(const float4*)&hiBase[(long)r*NPROJ + kk + qL*4];
            *(float2*)&His[r][qL*4]     = make_float2(va.x, va.y);
            *(float2*)&His[r][qL*4 + 2] = make_float2(va.z, va.w);
            float4 vb = *(const float4*)&hjBase[(long)r*NPROJ + kk + qL*4];
            *(float2*)&Hjs[r][qL*4]     = make_float2(vb.x, vb.y);
            *(float2*)&Hjs[r][qL*4 + 2] = make_float2(vb.z, vb.w);
        }
        __syncthreads();
#pragma unroll 8
        for (int hp = 0; hp < 16; hp++) {
            ull wp = *(const ull*)&w2s[kk + 2*hp];
            ull a[4], bb[4];
#pragma unroll
            for (int i = 0; i < 4; i++) a[i]  = *(const ull*)&His[ty*4 + i][2*hp];
#pragma unroll
            for (int g = 0; g < 4; g++) bb[g] = *(const ull*)&Hjs[tx + 16*g][2*hp];
#pragma unroll
            for (int i = 0; i < 4; i++)
#pragma unroll
                for (int g = 0; g < 4; g++) {
                    ull s = add2(a[i], bb[g]);
                    ull u = add2(s, s & ABS2);        // x + |x| = 2*relu(x)
                    acc2[i][g] = fma2(u, wp, acc2[i][g]);
                }
        }
    }
    float* out = g_scores + (long)b * NS * NS;
#pragma unroll
    for (int i = 0; i < 4; i++) {
        int gi = i0 + ty*4 + i;
#pragma unroll
        for (int g = 0; g < 4; g++) {
            float lo, hi;
            up2(acc2[i][g], lo, hi);
            out[(long)gi*NS + j0 + tx + 16*g] = lo + hi + b2v;
        }
    }
}

// ---------------- masked softmax: warp per row, chunk-trimmed -------------
__global__ __launch_bounds__(256)
void softmax_kernel() {
    const int warp = threadIdx.x >> 5, lane = threadIdx.x & 31;
    const int row = blockIdx.x * 8 + warp;    // b*512 + i
    const int i = row & (NS - 1);
    float4* s4 = (float4*)(g_scores + (long)row * NS);
    if (i == 0) {
        s4[lane] = make_float4(0.f, 0.f, 0.f, 0.f);   // chunk 0 only (K<=64 read)
        return;
    }
    const int lim = ((i >> 6) + 1) << 6;      // roundup64(i+1)
    const int nch = (lim + 127) >> 7;         // chunks of 128 cols
    float e[16];
    float m = -3.0e38f;
#pragma unroll
    for (int c = 0; c < 4; c++) {
        if (c < nch) {
            float4 v = s4[c*32 + lane];
            int jb = (c*32 + lane)*4;
            float a0 = (jb+0 < i) ? v.x : -3.0e38f;
            float a1 = (jb+1 < i) ? v.y : -3.0e38f;
            float a2 = (jb+2 < i) ? v.z : -3.0e38f;
            float a3 = (jb+3 < i) ? v.w : -3.0e38f;
            e[c*4+0]=a0; e[c*4+1]=a1; e[c*4+2]=a2; e[c*4+3]=a3;
            m = fmaxf(m, fmaxf(fmaxf(a0,a1), fmaxf(a2,a3)));
        }
    }
#pragma unroll
    for (int off = 16; off > 0; off >>= 1)
        m = fmaxf(m, __shfl_xor_sync(0xffffffffu, m, off));
    float sum = 0.f;
#pragma unroll
    for (int c = 0; c < 4; c++) {
        if (c < nch) {
#pragma unroll
            for (int q = 0; q < 4; q++) {
                float ev = (e[c*4+q] > -1.0e38f) ? __expf(e[c*4+q] - m) : 0.f;
                e[c*4+q] = ev; sum += ev;
            }
        }
    }
#pragma unroll
    for (int off = 16; off > 0; off >>= 1)
        sum += __shfl_xor_sync(0xffffffffu, sum, off);
    float inv = 1.f / sum;
#pragma unroll
    for (int c = 0; c < 4; c++)
        if (c < nch)
            s4[c*32 + lane] = make_float4(e[c*4+0]*inv, e[c*4+1]*inv,
                                          e[c*4+2]*inv, e[c*4+3]*inv);
}

// ---------------- layernorm -> d_out (shuffle reductions) -----------------
__global__ __launch_bounds__(256)
void ln_kernel(const float* __restrict__ gamma, const float* __restrict__ beta,
               float* __restrict__ out) {
    const int row = blockIdx.x;
    const int tid = threadIdx.x;
    const int lane = tid & 31, warp = tid >> 5;
    __shared__ float r1[8], r2[8];
    float v = g_preln[(long)row*ND + tid];
    float s = v;
#pragma unroll
    for (int off = 16; off > 0; off >>= 1)
        s += __shfl_xor_sync(0xffffffffu, s, off);
    if (lane == 0) r1[warp] = s;
    __syncthreads();
    float tot = 0.f;
#pragma unroll
    for (int w = 0; w < 8; w++) tot += r1[w];
    float mu = tot * (1.f / ND);
    float d = v - mu;
    float q = d * d;
#pragma unroll
    for (int off = 16; off > 0; off >>= 1)
        q += __shfl_xor_sync(0xffffffffu, q, off);
    if (lane == 0) r2[warp] = q;
    __syncthreads();
    float var = 0.f;
#pragma unroll
    for (int w = 0; w < 8; w++) var += r2[w];
    var *= (1.f / ND);
    float r = rsqrtf(var + 1e-5f);
    out[(long)row*ND + tid] = d * r * gamma[tid] + beta[tid];
}

// ---------------- launch ---------------------------------------------------
extern "C" void kernel_launch(void* const* d_in, const int* in_sizes, int n_in,
                              void* d_out, int out_size) {
    const float* x     = (const float*)d_in[0];
    const float* W1    = (const float*)d_in[1];
    const float* b1    = (const float*)d_in[2];
    const float* w2    = (const float*)d_in[3];
    const float* b2    = (const float*)d_in[4];
    const float* Wv    = (const float*)d_in[5];
    const float* bv    = (const float*)d_in[6];
    const float* Wo    = (const float*)d_in[7];
    const float* bo    = (const float*)d_in[8];
    const float* gamma = (const float*)d_in[9];
    const float* beta  = (const float*)d_in[10];
    float* out = (float*)d_out;

    static float *pBeff = nullptr, *pBiasN = nullptr, *pProj = nullptr,
                 *pScores = nullptr, *pPre = nullptr;
    if (!pBeff) {   // pure symbol lookups, cached before capture
        cudaGetSymbolAddress((void**)&pBeff,   g_Beff);
        cudaGetSymbolAddress((void**)&pBiasN,  g_biasN);
        cudaGetSymbolAddress((void**)&pProj,   g_proj);
        cudaGetSymbolAddress((void**)&pScores, g_scores);
        cudaGetSymbolAddress((void**)&pPre,    g_preln);
    }

    // 1a. pack cols 0..511 of Beff + biasN[0..511]
    pack_kernel<<<512, 256>>>(W1, b1);
    // 1b. biasN[512..767] = bv @ Wo
    bvwo_kernel<<<8, 256>>>(bv, Wo);
    // 1c. Beff cols 512..767 = Wv @ Wo   (16 blocks, K=256)
    sgemm_kernel<<<dim3(4, 4, 1), 256>>>(
        Wv, ND, 0, Wo, ND, 0, pBeff + 2*ND, NPROJ, 0, ND, 0,
        nullptr, nullptr, 0, 0);

    // 2. fused projection: proj[2048,768] = x @ Beff + biasN   (384 blocks)
    sgemm_kernel<<<dim3(NPROJ/64, NROWS/64, 1), 256>>>(
        x, ND, 0, pBeff, NPROJ, 0, pProj, NPROJ, 0, ND, 0,
        pBiasN, nullptr, 0, 0);

    // 3. pairwise relu-dot scores (lower-tri tiles only)
    scores_kernel<<<dim3(36, NB), 256>>>(w2, b2);

    // 4. masked softmax (warp per row, chunk-trimmed)
    softmax_kernel<<<NROWS/8, 256>>>();

    // 5. preln = attn @ vWo + bo + x   (batched, causal; 128 blocks)
    sgemm_kernel<<<dim3(ND/64, NS/64, NB), 256>>>(
        pScores, NS, (long)NS*NS,
        pProj + 2*ND, NPROJ, (long)NS*NPROJ,
        pPre, ND, (long)NS*ND,
        NS, 1, bo, x, ND, (long)NS*ND);

    // 6. layernorm -> d_out
    ln_kernel<<<NROWS, 256>>>(gamma, beta, out);
}